// round 1
// baseline (speedup 1.0000x reference)
#include <cuda_runtime.h>
#include <cstdint>
#include <math.h>

// GAT layer, fully fused:
//   H = X W  (tf32 mma, per-warp 16x128x256 GEMM, H lives in C-fragments)
//   e[i,j] = leakyrelu(s_i[i]+s_j[j]) masked by adj; alpha = softmax_j
//   out = elu(alpha @ H)
// One warp == one batch. 8 batches per CTA. W staged in smem per 64-wide K chunk.

#define B_TOT   32768
#define N_NODE  12
#define F_IN    256
#define D_OUT   128
#define BPC     8          // batches (warps) per CTA
#define KC      64         // K chunk staged in smem
#define WS_STRIDE 136      // bank-conflict-free: bank = (8k+n)%32 bijective

__device__ __forceinline__ uint32_t f2tf32(float f) {
    uint32_t r;
    asm("cvt.rna.tf32.f32 %0, %1;" : "=r"(r) : "f"(f));
    return r;
}

__device__ __forceinline__ void mma_tf32(float& c0, float& c1, float& c2, float& c3,
                                         uint32_t a0, uint32_t a1, uint32_t a2, uint32_t a3,
                                         uint32_t b0, uint32_t b1) {
    asm("mma.sync.aligned.m16n8k8.row.col.f32.tf32.tf32.f32 "
        "{%0,%1,%2,%3},{%4,%5,%6,%7},{%8,%9},{%0,%1,%2,%3};"
        : "+f"(c0), "+f"(c1), "+f"(c2), "+f"(c3)
        : "r"(a0), "r"(a1), "r"(a2), "r"(a3), "r"(b0), "r"(b1));
}

__device__ __forceinline__ float elu_f(float v) {
    return v > 0.f ? v : expm1f(v);
}

__global__ void __launch_bounds__(256, 1)
gat_fused_kernel(const float* __restrict__ x,    // [B, N, F]
                 const float* __restrict__ adj,  // [N, N]
                 const float* __restrict__ W,    // [F, D]
                 const float* __restrict__ a,    // [2D, 1]
                 float* __restrict__ out)        // [B, N, D]
{
    __shared__ uint32_t Ws[KC * WS_STRIDE];   // tf32 bits, [k][n] with stride 136
    __shared__ float sA[2 * D_OUT];           // a vector
    __shared__ float adjS[N_NODE * N_NODE];
    __shared__ float sjS[BPC][16];
    __shared__ float siS[BPC][16];

    const int tid  = threadIdx.x;
    const int w    = tid >> 5;
    const int lane = tid & 31;
    const int q    = lane >> 2;   // group id (rows r0=q, r1=q+8)
    const int m    = lane & 3;    // thread-in-group
    const int b    = blockIdx.x * BPC + w;

    sA[tid] = a[tid];                       // 256 threads, 256 elems
    if (tid < N_NODE * N_NODE) adjS[tid] = adj[tid];

    const int r0 = q;
    const int r1 = q + 8;
    const bool v1 = (r1 < N_NODE);          // rows 12..15 are padding

    const float* xb = x + (size_t)b * N_NODE * F_IN;

    // ---- GEMM: H = x_b @ W, per-warp 16x128, K=256 -------------------------
    float acc[16][4];
    #pragma unroll
    for (int t = 0; t < 16; t++) { acc[t][0] = acc[t][1] = acc[t][2] = acc[t][3] = 0.f; }

    for (int kc = 0; kc < F_IN; kc += KC) {
        // stage W chunk -> smem (tf32), coalesced
        for (int i = tid; i < KC * D_OUT; i += 256) {
            int k = i >> 7;       // 0..63
            int n = i & 127;
            Ws[k * WS_STRIDE + n] = f2tf32(W[(kc + k) * D_OUT + n]);
        }
        __syncthreads();

        #pragma unroll
        for (int ks = 0; ks < KC / 8; ks++) {
            const int k0 = kc + ks * 8;
            // A fragment (row-major 16x8): rows q / q+8, cols m / m+4
            uint32_t a0 = f2tf32(xb[r0 * F_IN + k0 + m]);
            uint32_t a2 = f2tf32(xb[r0 * F_IN + k0 + m + 4]);
            uint32_t a1 = v1 ? f2tf32(xb[r1 * F_IN + k0 + m])     : 0u;
            uint32_t a3 = v1 ? f2tf32(xb[r1 * F_IN + k0 + m + 4]) : 0u;

            #pragma unroll
            for (int t = 0; t < 16; t++) {
                // B fragment (col-major 8x8): row k = m / m+4, col n = q (+8t)
                uint32_t b0 = Ws[(ks * 8 + m)     * WS_STRIDE + 8 * t + q];
                uint32_t b1 = Ws[(ks * 8 + m + 4) * WS_STRIDE + 8 * t + q];
                mma_tf32(acc[t][0], acc[t][1], acc[t][2], acc[t][3],
                         a0, a1, a2, a3, b0, b1);
            }
        }
        __syncthreads();
    }

    // C-fragment layout: acc[t][0] = H[r0][8t+2m], [1] = H[r0][8t+2m+1],
    //                    acc[t][2] = H[r1][8t+2m], [3] = H[r1][8t+2m+1]

    // ---- s_i / s_j dot products -------------------------------------------
    float pj0 = 0.f, pi0 = 0.f, pj1 = 0.f, pi1 = 0.f;
    #pragma unroll
    for (int t = 0; t < 16; t++) {
        int c0 = 8 * t + 2 * m;
        float aj0 = sA[c0],         aj1 = sA[c0 + 1];
        float ai0 = sA[D_OUT + c0], ai1 = sA[D_OUT + c0 + 1];
        pj0 += acc[t][0] * aj0 + acc[t][1] * aj1;
        pi0 += acc[t][0] * ai0 + acc[t][1] * ai1;
        pj1 += acc[t][2] * aj0 + acc[t][3] * aj1;
        pi1 += acc[t][2] * ai0 + acc[t][3] * ai1;
    }
    // reduce over the 4 threads sharing a row
    #pragma unroll
    for (int off = 1; off < 4; off <<= 1) {
        pj0 += __shfl_xor_sync(0xffffffffu, pj0, off);
        pi0 += __shfl_xor_sync(0xffffffffu, pi0, off);
        pj1 += __shfl_xor_sync(0xffffffffu, pj1, off);
        pi1 += __shfl_xor_sync(0xffffffffu, pi1, off);
    }
    if (m == 0) {
        sjS[w][r0] = pj0; siS[w][r0] = pi0;
        sjS[w][r1] = pj1; siS[w][r1] = pi1;   // r1 up to 15 -> padding slots
    }
    __syncwarp();

    // ---- masked softmax rows (each lane computes its own rows) ------------
    float al0[N_NODE], al1[N_NODE];
    {
        // row r0 (always valid: r0 < 8)
        float sii = siS[w][r0];
        float ev[N_NODE];
        float mx = -INFINITY;
        #pragma unroll
        for (int j = 0; j < N_NODE; j++) {
            float e = sii + sjS[w][j];
            e = e > 0.f ? e : 0.2f * e;
            ev[j] = (adjS[r0 * N_NODE + j] == 1.0f) ? e : -INFINITY;
            mx = fmaxf(mx, ev[j]);
        }
        float sum = 0.f;
        #pragma unroll
        for (int j = 0; j < N_NODE; j++) { al0[j] = __expf(ev[j] - mx); sum += al0[j]; }
        float inv = 1.f / sum;
        #pragma unroll
        for (int j = 0; j < N_NODE; j++) al0[j] *= inv;
    }
    if (v1) {
        float sii = siS[w][r1];
        float ev[N_NODE];
        float mx = -INFINITY;
        #pragma unroll
        for (int j = 0; j < N_NODE; j++) {
            float e = sii + sjS[w][j];
            e = e > 0.f ? e : 0.2f * e;
            ev[j] = (adjS[r1 * N_NODE + j] == 1.0f) ? e : -INFINITY;
            mx = fmaxf(mx, ev[j]);
        }
        float sum = 0.f;
        #pragma unroll
        for (int j = 0; j < N_NODE; j++) { al1[j] = __expf(ev[j] - mx); sum += al1[j]; }
        float inv = 1.f / sum;
        #pragma unroll
        for (int j = 0; j < N_NODE; j++) al1[j] *= inv;
    } else {
        #pragma unroll
        for (int j = 0; j < N_NODE; j++) al1[j] = 0.f;
    }

    // ---- h' = alpha @ H via shuffles, elu, store --------------------------
    float* ob0 = out + ((size_t)b * N_NODE + r0) * D_OUT;
    float* ob1 = out + ((size_t)b * N_NODE + r1) * D_OUT;

    #pragma unroll
    for (int t = 0; t < 16; t++) {
        float o00 = 0.f, o01 = 0.f, o10 = 0.f, o11 = 0.f;
        #pragma unroll
        for (int j = 0; j < N_NODE; j++) {
            const int srcLane = ((j & 7) << 2) + m;
            float v0 = __shfl_sync(0xffffffffu, (j < 8) ? acc[t][0] : acc[t][2], srcLane);
            float v1s = __shfl_sync(0xffffffffu, (j < 8) ? acc[t][1] : acc[t][3], srcLane);
            o00 += al0[j] * v0;  o01 += al0[j] * v1s;
            o10 += al1[j] * v0;  o11 += al1[j] * v1s;
        }
        const int col = 8 * t + 2 * m;
        float2 s0 = make_float2(elu_f(o00), elu_f(o01));
        *reinterpret_cast<float2*>(ob0 + col) = s0;
        if (v1) {
            float2 s1 = make_float2(elu_f(o10), elu_f(o11));
            *reinterpret_cast<float2*>(ob1 + col) = s1;
        }
    }
}

extern "C" void kernel_launch(void* const* d_in, const int* in_sizes, int n_in,
                              void* d_out, int out_size) {
    const float* x   = (const float*)d_in[0];   // [32768,12,256]
    const float* adj = (const float*)d_in[1];   // [12,12]
    const float* W   = (const float*)d_in[2];   // [256,128]
    const float* a   = (const float*)d_in[3];   // [256,1]
    float* out       = (float*)d_out;           // [32768,12,128]

    gat_fused_kernel<<<B_TOT / BPC, 256>>>(x, adj, W, a, out);
}

// round 3
// speedup vs baseline: 1.6911x; 1.6911x over previous
#include <cuda_runtime.h>
#include <cstdint>
#include <math.h>

// GAT layer, fully fused, v2:
//   H = X W  (tf32 mma, per-warp 16x128x256 GEMM, H in C-fragments)
//   A and B fragments pre-swizzled in smem -> LDS.128 loads only in mainloop.
//   attention (masked softmax over 12 neighbors) + alpha@H via shuffles.
// One warp == one batch, 8 batches/CTA, 2 CTAs/SM.

#define B_TOT   32768
#define N_NODE  12
#define F_IN    256
#define D_OUT   128
#define BPC     8
#define KC      64
#define BLK     132            // words per fragment-block (128 used + 4 pad for bank skew)

__device__ __forceinline__ uint32_t f2tf32(float f) {
    uint32_t r;
    asm("cvt.rna.tf32.f32 %0, %1;" : "=r"(r) : "f"(f));
    return r;
}

__device__ __forceinline__ void mma_tf32(float& c0, float& c1, float& c2, float& c3,
                                         uint32_t a0, uint32_t a1, uint32_t a2, uint32_t a3,
                                         uint32_t b0, uint32_t b1) {
    asm("mma.sync.aligned.m16n8k8.row.col.f32.tf32.tf32.f32 "
        "{%0,%1,%2,%3},{%4,%5,%6,%7},{%8,%9},{%0,%1,%2,%3};"
        : "+f"(c0), "+f"(c1), "+f"(c2), "+f"(c3)
        : "r"(a0), "r"(a1), "r"(a2), "r"(a3), "r"(b0), "r"(b1));
}

__device__ __forceinline__ float elu_f(float v) {
    return v > 0.f ? v : expm1f(v);
}

// dynamic smem layout (words):
//   WsF : [8 ks][8 tp] blocks of BLK words; word = blk*BLK + lane*4 + vidx
//   XsF : [8 w][8 ks] blocks of BLK words
//   sA[256], adjS[144], sjS[8*16], siS[8*16]
#define WSF_WORDS (64 * BLK)
#define XSF_WORDS (64 * BLK)

__global__ void __launch_bounds__(256, 2)
gat_fused_kernel(const float* __restrict__ x,    // [B, N, F]
                 const float* __restrict__ adj,  // [N, N]
                 const float* __restrict__ W,    // [F, D]
                 const float* __restrict__ a,    // [2D, 1]
                 float* __restrict__ out)        // [B, N, D]
{
    extern __shared__ uint32_t smem[];
    uint32_t* WsF  = smem;
    uint32_t* XsF  = WsF + WSF_WORDS;
    float*    sA   = (float*)(XsF + XSF_WORDS);
    float*    adjS = sA + 2 * D_OUT;
    float*    sjS  = adjS + N_NODE * N_NODE;     // [8][16]
    float*    siS  = sjS + BPC * 16;             // [8][16]

    const int tid  = threadIdx.x;
    const int w    = tid >> 5;
    const int lane = tid & 31;
    const int q    = lane >> 2;
    const int m    = lane & 3;
    const int b    = blockIdx.x * BPC + w;

    sA[tid] = a[tid];
    if (tid < N_NODE * N_NODE) adjS[tid] = adj[tid];

    // zero XsF once (padding rows 12-15 stay zero forever)
    for (int i = tid; i < XSF_WORDS; i += 256) XsF[i] = 0u;
    __syncthreads();

    const int r0 = q;
    const int r1 = q + 8;
    const bool v1 = (r1 < N_NODE);

    float acc[16][4];
    #pragma unroll
    for (int t = 0; t < 16; t++) { acc[t][0] = acc[t][1] = acc[t][2] = acc[t][3] = 0.f; }

    for (int kc = 0; kc < F_IN; kc += KC) {
        // ---- stage W chunk into fragment order -----------------------------
        #pragma unroll
        for (int i = tid; i < 2048; i += 256) {
            int k  = i >> 5;                 // 0..63
            int c4 = i & 31;                 // float4 col index
            float4 wv = *(const float4*)(W + (size_t)(kc + k) * D_OUT + c4 * 4);
            int ks = k >> 3, mk = k & 7;
            int mm = mk & 3, hi = mk >> 2;
            int tp = c4 >> 2;
            int tl = (c4 >> 1) & 1;
            int vidx = tl * 2 + hi;
            uint32_t* base = WsF + (ks * 8 + tp) * BLK + vidx;
            float v[4] = {wv.x, wv.y, wv.z, wv.w};
            #pragma unroll
            for (int slot = 0; slot < 4; slot++) {
                int s  = (slot + c4) & 3;           // rotation: 2-way conflicts max
                int qq = 4 * (c4 & 1) + s;          // col within 8-group
                base[(qq * 4 + mm) * 4] = f2tf32(v[s]);
            }
        }
        // ---- stage x chunk (8 batches x 12 rows) into fragment order -------
        #pragma unroll
        for (int i = tid; i < 1536; i += 256) {
            int wb  = i / 192;
            int rem = i - wb * 192;
            int row = rem >> 4;              // 0..11
            int c4  = rem & 15;
            float4 xv = *(const float4*)(x +
                (((size_t)(blockIdx.x * BPC + wb) * N_NODE + row) * F_IN) + kc + c4 * 4);
            int ks = c4 >> 1, hi = c4 & 1;
            int qq = row & 7, rbit = row >> 3;
            int vidx = 2 * hi + rbit;
            uint32_t* base = XsF + (wb * 8 + ks) * BLK + qq * 16 + vidx;
            float v[4] = {xv.x, xv.y, xv.z, xv.w};
            #pragma unroll
            for (int s = 0; s < 4; s++) base[s * 4] = f2tf32(v[s]);   // m == s
        }
        __syncthreads();

        // ---- mainloop: 8 k-steps x 16 mma ---------------------------------
        const uint32_t* Xw = XsF + w * 8 * BLK + lane * 4;
        const uint32_t* Bp = WsF + lane * 4;
        #pragma unroll
        for (int ks = 0; ks < 8; ks++) {
            uint4 Af = *(const uint4*)(Xw + ks * BLK);
            #pragma unroll
            for (int tp = 0; tp < 8; tp++) {
                uint4 Bf = *(const uint4*)(Bp + (ks * 8 + tp) * BLK);
                mma_tf32(acc[2*tp][0],   acc[2*tp][1],   acc[2*tp][2],   acc[2*tp][3],
                         Af.x, Af.y, Af.z, Af.w, Bf.x, Bf.y);
                mma_tf32(acc[2*tp+1][0], acc[2*tp+1][1], acc[2*tp+1][2], acc[2*tp+1][3],
                         Af.x, Af.y, Af.z, Af.w, Bf.z, Bf.w);
            }
        }
        __syncthreads();
    }

    // C layout: acc[t][0]=H[r0][8t+2m], [1]=H[r0][8t+2m+1], [2]=H[r1][..], [3]=H[r1][..+1]

    // ---- s_i / s_j dot products -------------------------------------------
    float pj0 = 0.f, pi0 = 0.f, pj1 = 0.f, pi1 = 0.f;
    #pragma unroll
    for (int t = 0; t < 16; t++) {
        int c0 = 8 * t + 2 * m;
        float aj0 = sA[c0],         aj1 = sA[c0 + 1];
        float ai0 = sA[D_OUT + c0], ai1 = sA[D_OUT + c0 + 1];
        pj0 += acc[t][0] * aj0 + acc[t][1] * aj1;
        pi0 += acc[t][0] * ai0 + acc[t][1] * ai1;
        pj1 += acc[t][2] * aj0 + acc[t][3] * aj1;
        pi1 += acc[t][2] * ai0 + acc[t][3] * ai1;
    }
    #pragma unroll
    for (int off = 1; off < 4; off <<= 1) {
        pj0 += __shfl_xor_sync(0xffffffffu, pj0, off);
        pi0 += __shfl_xor_sync(0xffffffffu, pi0, off);
        pj1 += __shfl_xor_sync(0xffffffffu, pj1, off);
        pi1 += __shfl_xor_sync(0xffffffffu, pi1, off);
    }
    if (m == 0) {
        sjS[w * 16 + r0] = pj0; siS[w * 16 + r0] = pi0;
        sjS[w * 16 + r1] = pj1; siS[w * 16 + r1] = pi1;
    }
    __syncwarp();

    // ---- masked softmax (each lane: its rows r0 and r1) -------------------
    float al0[N_NODE], al1[N_NODE];
    {
        float sii = siS[w * 16 + r0];
        float ev[N_NODE];
        float mx = -INFINITY;
        #pragma unroll
        for (int j = 0; j < N_NODE; j++) {
            float e = sii + sjS[w * 16 + j];
            e = e > 0.f ? e : 0.2f * e;
            ev[j] = (adjS[r0 * N_NODE + j] == 1.0f) ? e : -INFINITY;
            mx = fmaxf(mx, ev[j]);
        }
        float sum = 0.f;
        #pragma unroll
        for (int j = 0; j < N_NODE; j++) { al0[j] = __expf(ev[j] - mx); sum += al0[j]; }
        float inv = 1.f / sum;
        #pragma unroll
        for (int j = 0; j < N_NODE; j++) al0[j] *= inv;
    }
    if (v1) {
        float sii = siS[w * 16 + r1];
        float ev[N_NODE];
        float mx = -INFINITY;
        #pragma unroll
        for (int j = 0; j < N_NODE; j++) {
            float e = sii + sjS[w * 16 + j];
            e = e > 0.f ? e : 0.2f * e;
            ev[j] = (adjS[r1 * N_NODE + j] == 1.0f) ? e : -INFINITY;
            mx = fmaxf(mx, ev[j]);
        }
        float sum = 0.f;
        #pragma unroll
        for (int j = 0; j < N_NODE; j++) { al1[j] = __expf(ev[j] - mx); sum += al1[j]; }
        float inv = 1.f / sum;
        #pragma unroll
        for (int j = 0; j < N_NODE; j++) al1[j] *= inv;
    } else {
        #pragma unroll
        for (int j = 0; j < N_NODE; j++) al1[j] = 0.f;
    }

    // ---- h' = alpha @ H via shuffles, elu, store --------------------------
    float* ob0 = out + ((size_t)b * N_NODE + r0) * D_OUT;
    float* ob1 = out + ((size_t)b * N_NODE + r1) * D_OUT;

    #pragma unroll
    for (int t = 0; t < 16; t++) {
        float o00 = 0.f, o01 = 0.f, o10 = 0.f, o11 = 0.f;
        #pragma unroll
        for (int j = 0; j < N_NODE; j++) {
            const int srcLane = ((j & 7) << 2) + m;
            float v0  = __shfl_sync(0xffffffffu, (j < 8) ? acc[t][0] : acc[t][2], srcLane);
            float v1s = __shfl_sync(0xffffffffu, (j < 8) ? acc[t][1] : acc[t][3], srcLane);
            o00 += al0[j] * v0;  o01 += al0[j] * v1s;
            o10 += al1[j] * v0;  o11 += al1[j] * v1s;
        }
        const int col = 8 * t + 2 * m;
        float2 s0 = make_float2(elu_f(o00), elu_f(o01));
        *reinterpret_cast<float2*>(ob0 + col) = s0;
        if (v1) {
            float2 s1 = make_float2(elu_f(o10), elu_f(o11));
            *reinterpret_cast<float2*>(ob1 + col) = s1;
        }
    }
}

extern "C" void kernel_launch(void* const* d_in, const int* in_sizes, int n_in,
                              void* d_out, int out_size) {
    const float* x   = (const float*)d_in[0];   // [32768,12,256]
    const float* adj = (const float*)d_in[1];   // [12,12]
    const float* W   = (const float*)d_in[2];   // [256,128]
    const float* a   = (const float*)d_in[3];   // [256,1]
    float* out       = (float*)d_out;           // [32768,12,128]

    const int smem_bytes =
        (WSF_WORDS + XSF_WORDS) * 4 +
        (2 * D_OUT + N_NODE * N_NODE + BPC * 16 * 2) * 4;

    cudaFuncSetAttribute(gat_fused_kernel,
                         cudaFuncAttributeMaxDynamicSharedMemorySize, smem_bytes);

    gat_fused_kernel<<<B_TOT / BPC, 256, smem_bytes>>>(x, adj, W, a, out);
}

// round 4
// speedup vs baseline: 1.8460x; 1.0916x over previous
#include <cuda_runtime.h>
#include <cstdint>
#include <math.h>

// GAT layer, fully fused, v3:
//   H = X W (tf32 mma). Warp = (batch-pair, D-half): 32x64 tile -> each B frag
//   feeds 4 mmas (halved B smem traffic). H spilled to smem once (reuses the
//   staging region), attention + alpha@H done with coalesced LDS/STG, no shuffles.

#define B_TOT   32768
#define N_NODE  12
#define F_IN    256
#define D_OUT   128
#define BPC     8
#define KC      64
#define BLK     132            // words per fragment-block (128 used + 4 pad)
#define HST     132            // Hs row stride (words)

#define WSF_WORDS (64 * BLK)
#define XSF_WORDS (64 * BLK)
#define HS_WORDS  (WSF_WORDS + XSF_WORDS)   // 16896 == 8 batches * 16 rows * 132

__device__ __forceinline__ uint32_t f2tf32(float f) {
    uint32_t r;
    asm("cvt.rna.tf32.f32 %0, %1;" : "=r"(r) : "f"(f));
    return r;
}

__device__ __forceinline__ void mma_tf32(float& c0, float& c1, float& c2, float& c3,
                                         uint32_t a0, uint32_t a1, uint32_t a2, uint32_t a3,
                                         uint32_t b0, uint32_t b1) {
    asm("mma.sync.aligned.m16n8k8.row.col.f32.tf32.tf32.f32 "
        "{%0,%1,%2,%3},{%4,%5,%6,%7},{%8,%9},{%0,%1,%2,%3};"
        : "+f"(c0), "+f"(c1), "+f"(c2), "+f"(c3)
        : "r"(a0), "r"(a1), "r"(a2), "r"(a3), "r"(b0), "r"(b1));
}

__device__ __forceinline__ float elu_f(float v) {
    return v > 0.f ? v : expm1f(v);
}

__global__ void __launch_bounds__(256, 2)
gat_fused_kernel(const float* __restrict__ x,    // [B, N, F]
                 const float* __restrict__ adj,  // [N, N]
                 const float* __restrict__ W,    // [F, D]
                 const float* __restrict__ a,    // [2D, 1]
                 float* __restrict__ out)        // [B, N, D]
{
    extern __shared__ uint32_t smem[];
    uint32_t* WsF    = smem;
    uint32_t* XsF    = WsF + WSF_WORDS;
    float*    Hs     = (float*)smem;                  // ALIASES WsF/XsF (post-GEMM)
    float*    sA     = (float*)(smem + HS_WORDS);
    float*    adjS   = sA + 2 * D_OUT;
    float*    alphaS = adjS + N_NODE * N_NODE;        // [8][16][12] stride 12, 1536 words

    const int tid  = threadIdx.x;
    const int w    = tid >> 5;
    const int lane = tid & 31;
    const int q    = lane >> 2;
    const int m    = lane & 3;
    const int p    = w >> 1;          // batch pair
    const int h    = w & 1;           // D half
    const int b    = blockIdx.x * BPC + w;   // batch for attention phase

    sA[tid] = a[tid];
    if (tid < N_NODE * N_NODE) adjS[tid] = adj[tid];

    // zero XsF once (padding rows 12-15 of each batch stay zero)
    for (int i = tid; i < XSF_WORDS; i += 256) XsF[i] = 0u;
    __syncthreads();

    // acc[tb][2*tp+tl][c] : batch 2p+tb, cols 64h+16tp+8tl+2m(+lo), rows q / q+8
    float acc[2][8][4];
    #pragma unroll
    for (int tb = 0; tb < 2; tb++)
        #pragma unroll
        for (int t = 0; t < 8; t++)
            acc[tb][t][0] = acc[tb][t][1] = acc[tb][t][2] = acc[tb][t][3] = 0.f;

    for (int kc = 0; kc < F_IN; kc += KC) {
        // ---- stage W chunk into fragment order -----------------------------
        #pragma unroll
        for (int i = tid; i < 2048; i += 256) {
            int k  = i >> 5;
            int c4 = i & 31;
            float4 wv = *(const float4*)(W + (size_t)(kc + k) * D_OUT + c4 * 4);
            int ks = k >> 3, mk = k & 7;
            int mm = mk & 3, hi = mk >> 2;
            int tp = c4 >> 2;
            int tl = (c4 >> 1) & 1;
            int vidx = tl * 2 + hi;
            uint32_t* base = WsF + (ks * 8 + tp) * BLK + vidx;
            float v[4] = {wv.x, wv.y, wv.z, wv.w};
            #pragma unroll
            for (int slot = 0; slot < 4; slot++) {
                int s  = (slot + c4) & 3;
                int qq = 4 * (c4 & 1) + s;
                base[(qq * 4 + mm) * 4] = f2tf32(v[s]);
            }
        }
        // ---- stage x chunk into fragment order -----------------------------
        #pragma unroll
        for (int i = tid; i < 1536; i += 256) {
            int wb  = i / 192;
            int rem = i - wb * 192;
            int row = rem >> 4;
            int c4  = rem & 15;
            float4 xv = *(const float4*)(x +
                (((size_t)(blockIdx.x * BPC + wb) * N_NODE + row) * F_IN) + kc + c4 * 4);
            int ks = c4 >> 1, hi = c4 & 1;
            int qq = row & 7, rbit = row >> 3;
            int vidx = 2 * hi + rbit;
            uint32_t* base = XsF + (wb * 8 + ks) * BLK + qq * 16 + vidx;
            float v[4] = {xv.x, xv.y, xv.z, xv.w};
            #pragma unroll
            for (int s = 0; s < 4; s++) base[s * 4] = f2tf32(v[s]);
        }
        __syncthreads();

        // ---- mainloop: 8 k-steps, 4 B frags each, 16 mmas -----------------
        const uint32_t* Xw0 = XsF + (2 * p)     * 8 * BLK + lane * 4;
        const uint32_t* Xw1 = XsF + (2 * p + 1) * 8 * BLK + lane * 4;
        const uint32_t* Bp  = WsF + lane * 4;
        #pragma unroll
        for (int ks = 0; ks < 8; ks++) {
            uint4 Af0 = *(const uint4*)(Xw0 + ks * BLK);
            uint4 Af1 = *(const uint4*)(Xw1 + ks * BLK);
            #pragma unroll
            for (int tp = 0; tp < 4; tp++) {
                uint4 Bf = *(const uint4*)(Bp + (ks * 8 + 4 * h + tp) * BLK);
                mma_tf32(acc[0][2*tp][0],   acc[0][2*tp][1],   acc[0][2*tp][2],   acc[0][2*tp][3],
                         Af0.x, Af0.y, Af0.z, Af0.w, Bf.x, Bf.y);
                mma_tf32(acc[0][2*tp+1][0], acc[0][2*tp+1][1], acc[0][2*tp+1][2], acc[0][2*tp+1][3],
                         Af0.x, Af0.y, Af0.z, Af0.w, Bf.z, Bf.w);
                mma_tf32(acc[1][2*tp][0],   acc[1][2*tp][1],   acc[1][2*tp][2],   acc[1][2*tp][3],
                         Af1.x, Af1.y, Af1.z, Af1.w, Bf.x, Bf.y);
                mma_tf32(acc[1][2*tp+1][0], acc[1][2*tp+1][1], acc[1][2*tp+1][2], acc[1][2*tp+1][3],
                         Af1.x, Af1.y, Af1.z, Af1.w, Bf.z, Bf.w);
            }
        }
        __syncthreads();
    }

    // ---- spill H to smem (reusing staging region) --------------------------
    #pragma unroll
    for (int tb = 0; tb < 2; tb++) {
        #pragma unroll
        for (int tp = 0; tp < 4; tp++) {
            #pragma unroll
            for (int tl = 0; tl < 2; tl++) {
                int ai  = 2 * tp + tl;
                int col = 64 * h + 16 * tp + 8 * tl + 2 * m;
                float* r0p = Hs + ((2 * p + tb) * 16 + q) * HST + col;
                *(float2*)r0p = make_float2(acc[tb][ai][0], acc[tb][ai][1]);
                *(float2*)(r0p + 8 * HST) = make_float2(acc[tb][ai][2], acc[tb][ai][3]);
            }
        }
    }
    __syncthreads();

    // ---- dots + masked softmax (warp w owns batch w; lane = row i) ---------
    float sj = 0.f, si = 0.f;
    if (lane < N_NODE) {
        const float4* hr = (const float4*)(Hs + (w * 16 + lane) * HST);
        const float4* ajp = (const float4*)sA;
        const float4* aip = (const float4*)(sA + D_OUT);
        #pragma unroll
        for (int c = 0; c < 32; c++) {
            float4 hv = hr[c];
            float4 av = ajp[c], bv = aip[c];
            sj += hv.x*av.x + hv.y*av.y + hv.z*av.z + hv.w*av.w;
            si += hv.x*bv.x + hv.y*bv.y + hv.z*bv.z + hv.w*bv.w;
        }
    }
    float sjv[N_NODE];
    #pragma unroll
    for (int j = 0; j < N_NODE; j++)
        sjv[j] = __shfl_sync(0xffffffffu, sj, j);

    if (lane < N_NODE) {
        float ev[N_NODE];
        float mx = -INFINITY;
        #pragma unroll
        for (int j = 0; j < N_NODE; j++) {
            float e = si + sjv[j];
            e = e > 0.f ? e : 0.2f * e;
            ev[j] = (adjS[lane * N_NODE + j] == 1.0f) ? e : -INFINITY;
            mx = fmaxf(mx, ev[j]);
        }
        float sum = 0.f;
        #pragma unroll
        for (int j = 0; j < N_NODE; j++) { ev[j] = __expf(ev[j] - mx); sum += ev[j]; }
        float inv = 1.f / sum;
        #pragma unroll
        for (int j = 0; j < N_NODE; j++)
            alphaS[w * 192 + lane * N_NODE + j] = ev[j] * inv;
    }
    __syncwarp();

    // ---- h' = alpha @ H (coalesced), elu, store ---------------------------
    float4 o[N_NODE];
    #pragma unroll
    for (int i = 0; i < N_NODE; i++) o[i] = make_float4(0.f, 0.f, 0.f, 0.f);

    const float* hb  = Hs + w * 16 * HST + lane * 4;
    const float* alw = alphaS + w * 192;
    #pragma unroll
    for (int j = 0; j < N_NODE; j++) {
        float4 hv = *(const float4*)(hb + j * HST);
        #pragma unroll
        for (int i = 0; i < N_NODE; i++) {
            float al = alw[i * N_NODE + j];
            o[i].x += al * hv.x;
            o[i].y += al * hv.y;
            o[i].z += al * hv.z;
            o[i].w += al * hv.w;
        }
    }
    #pragma unroll
    for (int i = 0; i < N_NODE; i++) {
        float4 r;
        r.x = elu_f(o[i].x);
        r.y = elu_f(o[i].y);
        r.z = elu_f(o[i].z);
        r.w = elu_f(o[i].w);
        *(float4*)(out + ((size_t)b * N_NODE + i) * D_OUT + lane * 4) = r;
    }
}

extern "C" void kernel_launch(void* const* d_in, const int* in_sizes, int n_in,
                              void* d_out, int out_size) {
    const float* x   = (const float*)d_in[0];   // [32768,12,256]
    const float* adj = (const float*)d_in[1];   // [12,12]
    const float* W   = (const float*)d_in[2];   // [256,128]
    const float* a   = (const float*)d_in[3];   // [256,1]
    float* out       = (float*)d_out;           // [32768,12,128]

    const int smem_bytes =
        (HS_WORDS + 2 * D_OUT + N_NODE * N_NODE + BPC * 192) * 4;

    cudaFuncSetAttribute(gat_fused_kernel,
                         cudaFuncAttributeMaxDynamicSharedMemorySize, smem_bytes);

    gat_fused_kernel<<<B_TOT / BPC, 256, smem_bytes>>>(x, adj, W, a, out);
}

// round 6
// speedup vs baseline: 2.1502x; 1.1648x over previous
#include <cuda_runtime.h>
#include <cstdint>
#include <math.h>

// GAT layer, v5 (mma.sync path — tcgen05 unavailable: build targets sm_103 non-'a'):
//   v3 tiling (warp = batch-pair x D-half, 32x64 tile) with:
//   - W fragments precomputed once (tf32, fragment-ordered) -> cp.async 16B staging
//   - X staged as raw fp32 bits (tf32 HW truncation), 4B cp.async, per-warp
//   - smem H spill + coalesced attention epilogue (unchanged from v3)

#define B_TOT   32768
#define N_NODE  12
#define F_IN    256
#define D_OUT   128
#define BPC     8
#define KC      64
#define BLK     132            // words per fragment-block (128 used + 4 pad)
#define HST     132            // Hs row stride (words)

#define WSF_WORDS (64 * BLK)   // 8448
#define XSF_WORDS (64 * BLK)   // 8448
#define HS_WORDS  (WSF_WORDS + XSF_WORDS)   // 16896 = 128 rows * 132

__device__ uint32_t WtF_g[4 * 64 * 32 * 4];   // [chunk][blk][lane][v] tf32 bits

__device__ __forceinline__ uint32_t f2tf32(float f) {
    uint32_t r;
    asm("cvt.rna.tf32.f32 %0, %1;" : "=r"(r) : "f"(f));
    return r;
}

__device__ __forceinline__ void mma_tf32(float& c0, float& c1, float& c2, float& c3,
                                         uint32_t a0, uint32_t a1, uint32_t a2, uint32_t a3,
                                         uint32_t b0, uint32_t b1) {
    asm("mma.sync.aligned.m16n8k8.row.col.f32.tf32.tf32.f32 "
        "{%0,%1,%2,%3},{%4,%5,%6,%7},{%8,%9},{%0,%1,%2,%3};"
        : "+f"(c0), "+f"(c1), "+f"(c2), "+f"(c3)
        : "r"(a0), "r"(a1), "r"(a2), "r"(a3), "r"(b0), "r"(b1));
}

__device__ __forceinline__ uint32_t smem_u32(const void* p) {
    uint32_t a;
    asm("{ .reg .u64 t; cvta.to.shared.u64 t, %1; cvt.u32.u64 %0, t; }" : "=r"(a) : "l"(p));
    return a;
}

__device__ __forceinline__ void cp16(uint32_t dst, const void* src) {
    asm volatile("cp.async.ca.shared.global [%0], [%1], 16;" :: "r"(dst), "l"(src));
}
__device__ __forceinline__ void cp4(uint32_t dst, const void* src) {
    asm volatile("cp.async.ca.shared.global [%0], [%1], 4;" :: "r"(dst), "l"(src));
}
__device__ __forceinline__ void cp_commit_wait() {
    asm volatile("cp.async.commit_group;");
    asm volatile("cp.async.wait_group 0;" ::: "memory");
}

__device__ __forceinline__ float elu_f(float v) {
    return v > 0.f ? v : expm1f(v);
}

// ---- pre-kernel: fragment-ordered tf32 W ----------------------------------
// word (ch, blk=(ks,tp), lane=(qq,mm), v=(tl,hi)) = tf32(W[k][n]),
//   k = 64ch + 8ks + mm + 4hi,  n = 16tp + 8tl + qq
__global__ void wfrag_pre_kernel(const float* __restrict__ W) {
    int idx = blockIdx.x * 256 + threadIdx.x;      // 0..32767
    int v   = idx & 3;
    int l   = (idx >> 2) & 31;
    int blk = (idx >> 7) & 63;
    int ch  = idx >> 13;
    int qq = l >> 2, mm = l & 3;
    int tl = v >> 1, hi = v & 1;
    int ks = blk >> 3, tp = blk & 7;
    int k = ch * 64 + ks * 8 + mm + 4 * hi;
    int n = 16 * tp + 8 * tl + qq;
    WtF_g[idx] = f2tf32(W[k * D_OUT + n]);
}

__global__ void __launch_bounds__(256, 2)
gat_fused_kernel(const float* __restrict__ x,    // [B, N, F]
                 const float* __restrict__ adj,  // [N, N]
                 const float* __restrict__ a,    // [2D, 1]
                 float* __restrict__ out)        // [B, N, D]
{
    extern __shared__ uint32_t smem[];
    uint32_t* WsF    = smem;
    uint32_t* XsF    = WsF + WSF_WORDS;
    float*    Hs     = (float*)smem;              // aliases WsF/XsF post-GEMM
    float*    sA     = (float*)(smem + HS_WORDS);
    float*    adjS   = sA + 2 * D_OUT;
    float*    alphaS = adjS + N_NODE * N_NODE;    // [8][12][12] stride 12

    const uint32_t sbW = smem_u32(WsF);
    const uint32_t sbX = smem_u32(XsF);

    const int tid  = threadIdx.x;
    const int w    = tid >> 5;
    const int lane = tid & 31;
    const int p    = w >> 1;          // batch pair
    const int h    = w & 1;           // D half
    const int b    = blockIdx.x * BPC + w;

    sA[tid] = a[tid];
    if (tid < N_NODE * N_NODE) adjS[tid] = adj[tid];

    // zero XsF once (padding rows 12-15 of each batch stay zero)
    for (int i = tid; i < XSF_WORDS; i += 256) XsF[i] = 0u;
    __syncthreads();

    float acc[2][8][4];
    #pragma unroll
    for (int tb = 0; tb < 2; tb++)
        #pragma unroll
        for (int t = 0; t < 8; t++)
            acc[tb][t][0] = acc[tb][t][1] = acc[tb][t][2] = acc[tb][t][3] = 0.f;

    const float* xw = x + ((size_t)b * N_NODE) * F_IN;   // warp stages its own batch

    for (int c = 0; c < 4; c++) {
        // ---- stage W chunk: pure 16B async copies, conflict-free ----------
        const uint32_t* wsrc = WtF_g + c * 8192;
        #pragma unroll
        for (int it = 0; it < 8; it++) {
            int idx = it * 256 + tid;
            int blk = idx >> 5, l = idx & 31;
            cp16(sbW + (blk * BLK + l * 4) * 4, wsrc + idx * 4);
        }
        // ---- stage X chunk: raw fp32 bits, 4B async copies ----------------
        #pragma unroll
        for (int it = 0; it < 6; it++) {
            int il  = it * 32 + lane;      // 0..191 = 12 rows x 16 c4
            int row = il >> 4;
            int c4  = il & 15;
            const float* src = xw + row * F_IN + c * KC + 4 * c4;
            int ks = c4 >> 1, hi = c4 & 1;
            int qq = row & 7, rbit = row >> 3;
            uint32_t dst = sbX + ((w * 8 + ks) * BLK + qq * 16 + 2 * hi + rbit) * 4;
            #pragma unroll
            for (int s = 0; s < 4; s++) cp4(dst + s * 16, src + s);
        }
        cp_commit_wait();
        __syncthreads();

        // ---- mainloop: 8 k-steps, 4 B frags each, 16 mmas -----------------
        const uint32_t* Xw0 = XsF + (2 * p)     * 8 * BLK + lane * 4;
        const uint32_t* Xw1 = XsF + (2 * p + 1) * 8 * BLK + lane * 4;
        const uint32_t* Bp  = WsF + lane * 4;
        #pragma unroll
        for (int ks = 0; ks < 8; ks++) {
            uint4 Af0 = *(const uint4*)(Xw0 + ks * BLK);
            uint4 Af1 = *(const uint4*)(Xw1 + ks * BLK);
            #pragma unroll
            for (int tp = 0; tp < 4; tp++) {
                uint4 Bf = *(const uint4*)(Bp + (ks * 8 + 4 * h + tp) * BLK);
                mma_tf32(acc[0][2*tp][0],   acc[0][2*tp][1],   acc[0][2*tp][2],   acc[0][2*tp][3],
                         Af0.x, Af0.y, Af0.z, Af0.w, Bf.x, Bf.y);
                mma_tf32(acc[0][2*tp+1][0], acc[0][2*tp+1][1], acc[0][2*tp+1][2], acc[0][2*tp+1][3],
                         Af0.x, Af0.y, Af0.z, Af0.w, Bf.z, Bf.w);
                mma_tf32(acc[1][2*tp][0],   acc[1][2*tp][1],   acc[1][2*tp][2],   acc[1][2*tp][3],
                         Af1.x, Af1.y, Af1.z, Af1.w, Bf.x, Bf.y);
                mma_tf32(acc[1][2*tp+1][0], acc[1][2*tp+1][1], acc[1][2*tp+1][2], acc[1][2*tp+1][3],
                         Af1.x, Af1.y, Af1.z, Af1.w, Bf.z, Bf.w);
            }
        }
        __syncthreads();
    }

    // ---- spill H to smem (reusing staging region) --------------------------
    const int q = lane >> 2;
    const int m = lane & 3;
    #pragma unroll
    for (int tb = 0; tb < 2; tb++) {
        #pragma unroll
        for (int tp = 0; tp < 4; tp++) {
            #pragma unroll
            for (int tl = 0; tl < 2; tl++) {
                int ai  = 2 * tp + tl;
                int col = 64 * h + 16 * tp + 8 * tl + 2 * m;
                float* r0p = Hs + ((2 * p + tb) * 16 + q) * HST + col;
                *(float2*)r0p = make_float2(acc[tb][ai][0], acc[tb][ai][1]);
                *(float2*)(r0p + 8 * HST) = make_float2(acc[tb][ai][2], acc[tb][ai][3]);
            }
        }
    }
    __syncthreads();

    // ---- dots + masked softmax (warp w owns batch w; lane = row i) ---------
    float sj = 0.f, si = 0.f;
    if (lane < N_NODE) {
        const float4* hr  = (const float4*)(Hs + (w * 16 + lane) * HST);
        const float4* ajp = (const float4*)sA;
        const float4* aip = (const float4*)(sA + D_OUT);
        #pragma unroll
        for (int cc = 0; cc < 32; cc++) {
            float4 hv = hr[cc];
            float4 av = ajp[cc], bv = aip[cc];
            sj += hv.x*av.x + hv.y*av.y + hv.z*av.z + hv.w*av.w;
            si += hv.x*bv.x + hv.y*bv.y + hv.z*bv.z + hv.w*bv.w;
        }
    }
    float sjv[N_NODE];
    #pragma unroll
    for (int j = 0; j < N_NODE; j++)
        sjv[j] = __shfl_sync(0xffffffffu, sj, j);

    if (lane < N_NODE) {
        float ev[N_NODE];
        float mx = -INFINITY;
        #pragma unroll
        for (int j = 0; j < N_NODE; j++) {
            float e = si + sjv[j];
            e = e > 0.f ? e : 0.2f * e;
            ev[j] = (adjS[lane * N_NODE + j] == 1.0f) ? e : -INFINITY;
            mx = fmaxf(mx, ev[j]);
        }
        float sum = 0.f;
        #pragma unroll
        for (int j = 0; j < N_NODE; j++) { ev[j] = __expf(ev[j] - mx); sum += ev[j]; }
        float inv = 1.f / sum;
        #pragma unroll
        for (int j = 0; j < N_NODE; j++)
            alphaS[w * 192 + lane * N_NODE + j] = ev[j] * inv;
    }
    __syncwarp();

    // ---- h' = alpha @ H (coalesced), elu, store ---------------------------
    float4 o[N_NODE];
    #pragma unroll
    for (int i = 0; i < N_NODE; i++) o[i] = make_float4(0.f, 0.f, 0.f, 0.f);

    const float* hb  = Hs + w * 16 * HST + lane * 4;
    const float* alw = alphaS + w * 192;
    #pragma unroll
    for (int j = 0; j < N_NODE; j++) {
        float4 hv = *(const float4*)(hb + j * HST);
        #pragma unroll
        for (int i = 0; i < N_NODE; i++) {
            float al = alw[i * N_NODE + j];
            o[i].x += al * hv.x;
            o[i].y += al * hv.y;
            o[i].z += al * hv.z;
            o[i].w += al * hv.w;
        }
    }
    #pragma unroll
    for (int i = 0; i < N_NODE; i++) {
        float4 r;
        r.x = elu_f(o[i].x);
        r.y = elu_f(o[i].y);
        r.z = elu_f(o[i].z);
        r.w = elu_f(o[i].w);
        *(float4*)(out + ((size_t)b * N_NODE + i) * D_OUT + lane * 4) = r;
    }
}

extern "C" void kernel_launch(void* const* d_in, const int* in_sizes, int n_in,
                              void* d_out, int out_size) {
    const float* x   = (const float*)d_in[0];   // [32768,12,256]
    const float* adj = (const float*)d_in[1];   // [12,12]
    const float* W   = (const float*)d_in[2];   // [256,128]
    const float* a   = (const float*)d_in[3];   // [256,1]
    float* out       = (float*)d_out;           // [32768,12,128]

    wfrag_pre_kernel<<<128, 256>>>(W);

    const int smem_bytes =
        (HS_WORDS + 2 * D_OUT + N_NODE * N_NODE + BPC * 192) * 4;

    cudaFuncSetAttribute(gat_fused_kernel,
                         cudaFuncAttributeMaxDynamicSharedMemorySize, smem_bytes);

    gat_fused_kernel<<<B_TOT / BPC, 256, smem_bytes>>>(x, adj, a, out);
}